// round 16
// baseline (speedup 1.0000x reference)
#include <cuda_runtime.h>
#include <cuda_bf16.h>
#include <cuda_fp16.h>
#include <math.h>
#include <float.h>
#include <stdint.h>

// Problem constants
#define BB 4
#define TT 1024
#define VV 32000
#define DD 1024
#define HH 16
#define DKK 64
#define BT 4096            // B*T
#define N3 3072            // 3*D (q|k|v)
#define BHN 64             // B*H
#define BTV 131072000LL    // BT*VV
#define NBLK 125           // VV / 256

// ---------------- scratch (device globals; no allocation) ----------------
__device__ float g_rowloss[BT];
__device__ float2 g_pml[(size_t)BT * NBLK];      // per (row, nblock) partial (max, sum)

__device__ __half g_x16[BT * DD];                // embedded input fp16 (QKV A)
__device__ __half g_w16[N3 * DD];                // Wqkv fp16 K-major [3072,1024]
__device__ __half g_q16[BHN * TT * DKK];         // q fp16 head-major [bh][t][dk]
__device__ __half g_k16[BHN * TT * DKK];         // k fp16
__device__ __half g_v16[BHN * TT * DKK];         // v fp16
__device__ __half g_ha[BT * DD];                 // attention-out fp16 (logits A)
__device__ __half g_hb[(size_t)VV * DD];         // Wo^T fp16 (K-major [32000,1024])

// ================= helpers =================
__device__ __forceinline__ uint32_t smem_to_u32(const void* p) {
    uint32_t a;
    asm("{ .reg .u64 t; cvta.to.shared.u64 t, %1; cvt.u32.u64 %0, t; }" : "=r"(a) : "l"(p));
    return a;
}
__device__ __forceinline__ void cp16(uint32_t saddr, const void* gptr) {
    asm volatile("cp.async.cg.shared.global [%0], [%1], 16;" :: "r"(saddr), "l"(gptr));
}
__device__ __forceinline__ void stg_cs_v2(float* p, float a, float b) {
    asm volatile("st.global.cs.v2.f32 [%0], {%1, %2};" :: "l"(p), "f"(a), "f"(b) : "memory");
}
#define LDSM_X4(R0, R1, R2, R3, addr) \
    asm volatile("ldmatrix.sync.aligned.m8n8.x4.shared.b16 {%0,%1,%2,%3}, [%4];" \
                 : "=r"(R0), "=r"(R1), "=r"(R2), "=r"(R3) : "r"(addr))
#define LDSM_X4_T(R0, R1, R2, R3, addr) \
    asm volatile("ldmatrix.sync.aligned.m8n8.x4.trans.shared.b16 {%0,%1,%2,%3}, [%4];" \
                 : "=r"(R0), "=r"(R1), "=r"(R2), "=r"(R3) : "r"(addr))

__device__ __forceinline__ void mma_f16(float* c,
                                        uint32_t a0, uint32_t a1, uint32_t a2, uint32_t a3,
                                        uint32_t b0, uint32_t b1)
{
    asm volatile(
        "mma.sync.aligned.m16n8k16.row.col.f32.f16.f16.f32 "
        "{%0,%1,%2,%3}, {%4,%5,%6,%7}, {%8,%9}, {%0,%1,%2,%3};"
        : "+f"(c[0]), "+f"(c[1]), "+f"(c[2]), "+f"(c[3])
        : "r"(a0), "r"(a1), "r"(a2), "r"(a3), "r"(b0), "r"(b1));
}
__device__ __forceinline__ uint32_t packh2(float a, float b) {
    __half2 h = __floats2half2_rn(a, b);
    return *(uint32_t*)&h;
}
// merge partial logsumexp (m2,s2) into (m,s); finite inputs only
__device__ __forceinline__ void lse_merge(float& m, float& s, float m2, float s2) {
    const float M = fmaxf(m, m2);
    s = s * __expf(m - M) + s2 * __expf(m2 - M);
    m = M;
}

// ============ shared constants ============
#define FPITCH 144
#define FARR (128 * FPITCH)          // 18432

// ============ QKV GEMM: 128x128 tile, BK=64, 3-stage, occ 2 ============
#define FSTAGE (2 * FARR)            // 36864
#define FSMEM (3 * FSTAGE)           // 110592
#define FOFF_A 0
#define FOFF_B FARR

__global__ __launch_bounds__(256, 2)
void k_gemm_qkv16(const __half* __restrict__ A, const __half* __restrict__ B,
                  const float* __restrict__ bq, const float* __restrict__ bk,
                  const float* __restrict__ bv)
{
    extern __shared__ char smem[];
    const uint32_t sbase = smem_to_u32(smem);
    const int tid = threadIdx.x;
    const int wid = tid >> 5, lid = tid & 31;
    const int g = lid >> 2, tig = lid & 3;
    const int wm = (wid >> 2) * 64;
    const int wn = (wid & 3) * 32;
    const int bm = blockIdx.x * 128;
    const int bn = blockIdx.y * 128;

    const uint32_t aRow = (uint32_t)((wm + (lid & 15)) * FPITCH + ((lid >> 4) << 4));
    const uint32_t bRow = (uint32_t)((wn + (lid & 7) + ((lid >> 4) << 3)) * FPITCH
                                     + (((lid >> 3) & 1) << 4));

    float acc[4][4][4];
    #pragma unroll
    for (int i = 0; i < 4; i++)
        #pragma unroll
        for (int j = 0; j < 4; j++)
            #pragma unroll
            for (int q = 0; q < 4; q++) acc[i][j][q] = 0.0f;

    auto load_stage = [&](int slot, int chunk) {
        const int k0 = chunk << 6;
        const uint32_t st = sbase + slot * FSTAGE;
        #pragma unroll
        for (int i = 0; i < 4; i++) {
            const int u = i * 256 + tid;
            const int r = u >> 3, cc = u & 7;
            const uint32_t sa = st + r * FPITCH + cc * 16;
            cp16(sa + FOFF_A, A + (size_t)(bm + r) * DD + k0 + cc * 8);
            cp16(sa + FOFF_B, B + (size_t)(bn + r) * DD + k0 + cc * 8);
        }
    };

    load_stage(0, 0);
    asm volatile("cp.async.commit_group;");
    load_stage(1, 1);
    asm volatile("cp.async.commit_group;");
    const int nchunks = DD >> 6;
    for (int c = 0; c < nchunks; c++) {
        if (c < nchunks - 1) asm volatile("cp.async.wait_group 1;");
        else                 asm volatile("cp.async.wait_group 0;");
        __syncthreads();
        if (c + 2 < nchunks) {
            load_stage((c + 2) % 3, c + 2);
            asm volatile("cp.async.commit_group;");
        }
        const uint32_t stg = sbase + (c % 3) * FSTAGE;
        #pragma unroll
        for (int ks = 0; ks < 4; ks++) {
            const uint32_t ko = (uint32_t)(ks * 32);
            uint32_t Af[4][4];
            #pragma unroll
            for (int mt = 0; mt < 4; mt++) {
                const uint32_t ra = stg + FOFF_A + aRow + ko + (uint32_t)(mt * 16 * FPITCH);
                LDSM_X4(Af[mt][0], Af[mt][1], Af[mt][2], Af[mt][3], ra);
            }
            uint32_t Bf[4][2];
            {
                const uint32_t rb0 = stg + FOFF_B + bRow + ko;
                const uint32_t rb1 = rb0 + (uint32_t)(16 * FPITCH);
                LDSM_X4(Bf[0][0], Bf[0][1], Bf[1][0], Bf[1][1], rb0);
                LDSM_X4(Bf[2][0], Bf[2][1], Bf[3][0], Bf[3][1], rb1);
            }
            #pragma unroll
            for (int mt = 0; mt < 4; mt++)
                #pragma unroll
                for (int nt = 0; nt < 4; nt++)
                    mma_f16(acc[mt][nt], Af[mt][0], Af[mt][1], Af[mt][2], Af[mt][3],
                            Bf[nt][0], Bf[nt][1]);
        }
    }

    #pragma unroll
    for (int mt = 0; mt < 4; mt++) {
        const int row = bm + wm + mt * 16 + g;     // token
        const int b_ = row >> 10, t_ = row & 1023;
        #pragma unroll
        for (int nt = 0; nt < 4; nt++) {
            const int col = bn + wn + nt * 8 + tig * 2;
            const int sel = col >> 10, hc = col & 1023;
            const float* bsrc = (sel == 0) ? bq : (sel == 1) ? bk : bv;
            const float b0 = bsrc[hc], b1 = bsrc[hc + 1];
            const int h = hc >> 6, dk = hc & 63;
            __half* dst = (sel == 0) ? g_q16 : (sel == 1) ? g_k16 : g_v16;
            const size_t o0 = ((size_t)(b_ * HH + h) * TT + t_) * DKK + dk;
            *(__half2*)(dst + o0) =
                __floats2half2_rn(acc[mt][nt][0] + b0, acc[mt][nt][1] + b1);
            *(__half2*)(dst + o0 + 8 * DKK) =
                __floats2half2_rn(acc[mt][nt][2] + b0, acc[mt][nt][3] + b1);
        }
    }
}

// ============ Logits GEMM: 128x256 tile, BK=64, 3-stage, occ 1 ============
// Warp tile 64x64 -> 32 independent MMAs per ks-step (2x ILP vs 128x128).
#define F2OFF_A 0
#define F2OFF_B FARR                  // A: 128 rows, B: 256 rows
#define F2STAGE (3 * FARR)            // 55296
#define F2SMEM (3 * F2STAGE)          // 165888

__global__ __launch_bounds__(256, 1)
void k_gemm_logits(const __half* __restrict__ A, const __half* __restrict__ B,
                   float* __restrict__ C, const float* __restrict__ bias)
{
    extern __shared__ char smem[];
    const uint32_t sbase = smem_to_u32(smem);
    const int tid = threadIdx.x;
    const int wid = tid >> 5, lid = tid & 31;
    const int g = lid >> 2, tig = lid & 3;
    const int wm = (wid >> 2) * 64;      // 0 or 64
    const int wn = (wid & 3) * 64;       // 0,64,128,192
    const int bm = blockIdx.x * 128;     // M fastest -> wave shares B tile
    const int bn = blockIdx.y * 256;

    const uint32_t aRow = (uint32_t)((wm + (lid & 15)) * FPITCH + ((lid >> 4) << 4));
    const uint32_t bRow = (uint32_t)((wn + (lid & 7) + ((lid >> 4) << 3)) * FPITCH
                                     + (((lid >> 3) & 1) << 4));

    float acc[4][8][4];
    #pragma unroll
    for (int i = 0; i < 4; i++)
        #pragma unroll
        for (int j = 0; j < 8; j++)
            #pragma unroll
            for (int q = 0; q < 4; q++) acc[i][j][q] = 0.0f;

    auto load_stage = [&](int slot, int chunk) {
        const int k0 = chunk << 6;
        const uint32_t st = sbase + slot * F2STAGE;
        #pragma unroll
        for (int i = 0; i < 4; i++) {      // A: 1024 16B-chunks
            const int u = i * 256 + tid;
            const int r = u >> 3, cc = u & 7;
            cp16(st + F2OFF_A + r * FPITCH + cc * 16,
                 A + (size_t)(bm + r) * DD + k0 + cc * 8);
        }
        #pragma unroll
        for (int i = 0; i < 8; i++) {      // B: 2048 16B-chunks
            const int u = i * 256 + tid;
            const int r = u >> 3, cc = u & 7;
            cp16(st + F2OFF_B + r * FPITCH + cc * 16,
                 B + (size_t)(bn + r) * DD + k0 + cc * 8);
        }
    };

    load_stage(0, 0);
    asm volatile("cp.async.commit_group;");
    load_stage(1, 1);
    asm volatile("cp.async.commit_group;");
    const int nchunks = DD >> 6;
    for (int c = 0; c < nchunks; c++) {
        if (c < nchunks - 1) asm volatile("cp.async.wait_group 1;");
        else                 asm volatile("cp.async.wait_group 0;");
        __syncthreads();
        if (c + 2 < nchunks) {
            load_stage((c + 2) % 3, c + 2);
            asm volatile("cp.async.commit_group;");
        }
        const uint32_t stg = sbase + (c % 3) * F2STAGE;
        #pragma unroll
        for (int ks = 0; ks < 4; ks++) {
            const uint32_t ko = (uint32_t)(ks * 32);
            uint32_t Af[4][4];
            #pragma unroll
            for (int mt = 0; mt < 4; mt++) {
                const uint32_t ra = stg + F2OFF_A + aRow + ko + (uint32_t)(mt * 16 * FPITCH);
                LDSM_X4(Af[mt][0], Af[mt][1], Af[mt][2], Af[mt][3], ra);
            }
            uint32_t Bf[8][2];
            #pragma unroll
            for (int jp = 0; jp < 4; jp++) {
                const uint32_t rb = stg + F2OFF_B + bRow + ko + (uint32_t)(jp * 16 * FPITCH);
                LDSM_X4(Bf[2 * jp][0], Bf[2 * jp][1], Bf[2 * jp + 1][0], Bf[2 * jp + 1][1], rb);
            }
            #pragma unroll
            for (int mt = 0; mt < 4; mt++)
                #pragma unroll
                for (int nt = 0; nt < 8; nt++)
                    mma_f16(acc[mt][nt], Af[mt][0], Af[mt][1], Af[mt][2], Af[mt][3],
                            Bf[nt][0], Bf[nt][1]);
        }
    }

    // epilogue: store logits (streaming) + per-row logsumexp partials
    __syncthreads();                    // smem stages dead; reuse for partials
    float2* part = (float2*)smem;       // [4 col-parts][128 rows]
    const int cpart = wid & 3;

    #pragma unroll
    for (int mt = 0; mt < 4; mt++) {
        const int lr = wm + mt * 16 + g;         // CTA-local row
        const int row = bm + lr;
        float m0 = -INFINITY, s0 = 0.0f, m1 = -INFINITY, s1 = 0.0f;
        #pragma unroll
        for (int nt = 0; nt < 8; nt++) {
            const int col = bn + wn + nt * 8 + tig * 2;
            const float b0 = bias[col], b1 = bias[col + 1];
            const float v00 = acc[mt][nt][0] + b0, v01 = acc[mt][nt][1] + b1;
            const float v10 = acc[mt][nt][2] + b0, v11 = acc[mt][nt][3] + b1;
            stg_cs_v2(C + (size_t)row * VV + col, v00, v01);
            stg_cs_v2(C + (size_t)(row + 8) * VV + col, v10, v11);
            const float mx0 = fmaxf(v00, v01);
            if (mx0 > m0) { s0 *= __expf(m0 - mx0); m0 = mx0; }
            s0 += __expf(v00 - m0) + __expf(v01 - m0);
            const float mx1 = fmaxf(v10, v11);
            if (mx1 > m1) { s1 *= __expf(m1 - mx1); m1 = mx1; }
            s1 += __expf(v10 - m1) + __expf(v11 - m1);
        }
        #pragma unroll
        for (int w = 1; w < 4; w <<= 1) {
            lse_merge(m0, s0, __shfl_xor_sync(0xFFFFFFFF, m0, w),
                              __shfl_xor_sync(0xFFFFFFFF, s0, w));
            lse_merge(m1, s1, __shfl_xor_sync(0xFFFFFFFF, m1, w),
                              __shfl_xor_sync(0xFFFFFFFF, s1, w));
        }
        if (tig == 0) {
            part[cpart * 128 + lr]     = make_float2(m0, s0);
            part[cpart * 128 + lr + 8] = make_float2(m1, s1);
        }
    }
    __syncthreads();

    if (tid < 128) {                    // one thread per CTA row
        float2 p = part[tid];
        float m = p.x, s = p.y;
        #pragma unroll
        for (int cp = 1; cp < 4; cp++) {
            const float2 q = part[cp * 128 + tid];
            lse_merge(m, s, q.x, q.y);
        }
        g_pml[(size_t)(bm + tid) * NBLK + blockIdx.y] = make_float2(m, s);
    }
}

// ---------------- embed -> fp16 ----------------
__global__ void k_embed16(const int* __restrict__ ids,
                          const float* __restrict__ tok_emb,
                          const float* __restrict__ pos_emb)
{
    int tok = blockIdx.x;
    int t = tok & (TT - 1);
    int v = ids[tok];
    const float* te = tok_emb + (size_t)v * DD;
    const float* pe = pos_emb + (size_t)t * DD;
    __half* xo = g_x16 + (size_t)tok * DD;
    for (int d = threadIdx.x; d < DD; d += blockDim.x)
        xo[d] = __float2half(te[d] * 32.0f + pe[d]);
}

// ---------------- repack Wq/Wk/Wv via smem transpose -> K-major fp16 ----------------
__global__ void k_repack_wqkvT(const float* __restrict__ Wq,
                               const float* __restrict__ Wk,
                               const float* __restrict__ Wv)
{
    __shared__ float s[32][33];
    const int sh = blockIdx.x;
    const int sel = sh >> 4, h = sh & 15;
    const int d0 = blockIdx.y * 32;
    const int k0 = blockIdx.z * 32;
    const float* src = (sel == 0) ? Wq : (sel == 1) ? Wk : Wv;
    const float* base = src + (size_t)h * (DD * DKK);
    const int tx = threadIdx.x, ty = threadIdx.y;
    #pragma unroll
    for (int i = 0; i < 4; i++)
        s[ty + i * 8][tx] = base[(size_t)(d0 + ty + i * 8) * DKK + k0 + tx];
    __syncthreads();
    #pragma unroll
    for (int i = 0; i < 4; i++) {
        const int k = k0 + ty + i * 8;
        const int n = sel * 1024 + h * 64 + k;
        const int d = d0 + tx;
        g_w16[(size_t)n * DD + d] = __float2half(s[tx][ty + i * 8]);
    }
}

// ---------------- transpose Wo [1024, 32000] -> fp16 [32000, 1024] ----------------
__global__ void k_woT(const float* __restrict__ Wo)
{
    __shared__ float s[32][33];
    int v0 = blockIdx.x * 32, d0 = blockIdx.y * 32;
    int tx = threadIdx.x, ty = threadIdx.y;  // (32, 8)
    #pragma unroll
    for (int i = 0; i < 4; i++)
        s[ty + i * 8][tx] = Wo[(size_t)(d0 + ty + i * 8) * VV + v0 + tx];
    __syncthreads();
    #pragma unroll
    for (int i = 0; i < 4; i++) {
        int v = v0 + ty + i * 8;
        int d = d0 + tx;
        g_hb[(size_t)v * DD + d] = __float2half(s[tx][ty + i * 8]);
    }
}

// ---------------- tensor-core flash attention (4-stage KV pipeline) ----------------
#define PL 144
#define FLK_BYTES (64 * PL)                  // 9216
#define FLQ_BYTES (128 * PL)                 // 18432
#define FL2_STAGE (2 * FLK_BYTES)            // 18432
#define FL2_SMEM (FLQ_BYTES + 4 * FL2_STAGE) // 92160

__global__ __launch_bounds__(256, 2)
void k_flash_tc()
{
    extern __shared__ char smem[];
    const uint32_t sbase = smem_to_u32(smem);
    const int tid = threadIdx.x;
    const int w = tid >> 5, lid = tid & 31;
    const int g = lid >> 2, tig = lid & 3;
    const int tT = 7 - (int)blockIdx.x;      // heavy tiles first
    const int bh = blockIdx.y;
    const int t0 = tT * 128;
    const int wr = w * 16;
    const int nb = t0 / 64 + 2;

    const __half* gq = g_q16 + (size_t)bh * TT * DKK;
    const __half* gk = g_k16 + (size_t)bh * TT * DKK;
    const __half* gv = g_v16 + (size_t)bh * TT * DKK;

    auto load_kv = [&](int slot, int s0) {
        const uint32_t st = sbase + FLQ_BYTES + slot * FL2_STAGE;
        #pragma unroll
        for (int i = 0; i < 2; i++) {
            int u = i * 256 + tid;
            int r = u >> 3, cc = u & 7;
            uint32_t sa = st + r * PL + cc * 16;
            cp16(sa, gk + (size_t)(s0 + r) * DKK + cc * 8);
            cp16(sa + FLK_BYTES, gv + (size_t)(s0 + r) * DKK + cc * 8);
        }
    };

    // Q load (grouped with first KV block)
    #pragma unroll
    for (int i = 0; i < 4; i++) {
        int u = i * 256 + tid;
        int r = u >> 3, cc = u & 7;
        cp16(sbase + r * PL + cc * 16, gq + (size_t)(t0 + r) * DKK + cc * 8);
    }
    // prime up to 3 stages
    int P = (nb < 3) ? nb : 3;          // next block to prefetch
    for (int p = 0; p < P; p++) {
        load_kv(p, p * 64);
        asm volatile("cp.async.commit_group;");
    }

    const uint32_t aoff = (uint32_t)((lid & 15) * PL + ((lid >> 4) << 4));
    const uint32_t boff = (uint32_t)(((lid & 7) + ((lid >> 4) << 3)) * PL
                                     + (((lid >> 3) & 1) << 4));
    const uint32_t voff = aoff;

    float O[8][4];
    #pragma unroll
    for (int j = 0; j < 8; j++)
        #pragma unroll
        for (int q = 0; q < 4; q++) O[j][q] = 0.0f;
    float m0 = -INFINITY, m1 = -INFINITY, l0 = 0.0f, l1 = 0.0f;

    const int trow0 = t0 + wr + g;
    const int trow1 = trow0 + 8;

    for (int c = 0; c < nb; c++) {
        const int s0 = c * 64;
        const int out = P - c - 1;      // groups allowed to stay in flight
        if (out >= 2)      asm volatile("cp.async.wait_group 2;");
        else if (out == 1) asm volatile("cp.async.wait_group 1;");
        else               asm volatile("cp.async.wait_group 0;");
        __syncthreads();
        if (P < nb) {
            load_kv(P & 3, P * 64);
            asm volatile("cp.async.commit_group;");
            P++;
        }

        if (s0 <= t0 + wr + 15) {
            const uint32_t stK = sbase + FLQ_BYTES + (c & 3) * FL2_STAGE;
            const uint32_t stV = stK + FLK_BYTES;

            uint32_t Af[4][4];
            #pragma unroll
            for (int ks = 0; ks < 4; ks++)
                LDSM_X4(Af[ks][0], Af[ks][1], Af[ks][2], Af[ks][3],
                        sbase + (uint32_t)(wr * PL) + aoff + ks * 32);
            float S[8][4];
            #pragma unroll
            for (int j = 0; j < 8; j++)
                #pragma unroll
                for (int q = 0; q < 4; q++) S[j][q] = 0.0f;
            #pragma unroll
            for (int ks = 0; ks < 4; ks++) {
                uint32_t Bf[8][2];
                #pragma unroll
                for (int jp = 0; jp < 4; jp++)
                    LDSM_X4(Bf[2 * jp][0], Bf[2 * jp][1], Bf[2 * jp + 1][0], Bf[2 * jp + 1][1],
                            stK + boff + (uint32_t)(jp * 16 * PL) + ks * 32);
                #pragma unroll
                for (int j = 0; j < 8; j++)
                    mma_f16(S[j], Af[ks][0], Af[ks][1], Af[ks][2], Af[ks][3],
                            Bf[j][0], Bf[j][1]);
            }

            const bool domask = (s0 + 63 > t0 + wr);
            #pragma unroll
            for (int j = 0; j < 8; j++) {
                #pragma unroll
                for (int q = 0; q < 4; q++) S[j][q] *= 0.125f;
                if (domask) {
                    const int sc = s0 + j * 8 + tig * 2;
                    if (sc     > trow0) S[j][0] = -INFINITY;
                    if (sc + 1 > trow0) S[j][1] = -INFINITY;
                    if (sc     > trow1) S[j][2] = -INFINITY;
                    if (sc + 1 > trow1) S[j][3] = -INFINITY;
                }
            }

            float rm0 = -INFINITY, rm1 = -INFINITY;
            #pragma unroll
            for (int j = 0; j < 8; j++) {
                rm0 = fmaxf(rm0, fmaxf(S[j][0], S[j][1]));
                rm1 = fmaxf(rm1, fmaxf(S[j][2], S[j][3]));
            }
            rm0 = fmaxf(rm0, __shfl_xor_sync(0xFFFFFFFF, rm0, 1));
            rm0 = fmaxf(rm0, __shfl_xor_sync(0xFFFFFFFF, rm0, 2));
            rm1 = fmaxf(rm1, __shfl_xor_sync(0xFFFFFFFF, rm1, 1));
            rm1 = fmaxf(rm1, __shfl_xor_sync(0xFFFFFFFF, rm1, 2));
            const float mn0 = fmaxf(m0, rm0), mn1 = fmaxf(m1, rm1);
            const float fac0 = __expf(m0 - mn0), fac1 = __expf(m1 - mn1);
            float rs0 = 0.0f, rs1 = 0.0f;
            #pragma unroll
            for (int j = 0; j < 8; j++) {
                S[j][0] = __expf(S[j][0] - mn0);
                S[j][1] = __expf(S[j][1] - mn0);
                S[j][2] = __expf(S[j][2] - mn1);
                S[j][3] = __expf(S[j][3] - mn1);
                rs0 += S[j][0] + S[j][1];
                rs1 += S[j][2] + S[j][3];
            }
            rs0 += __shfl_xor_sync(0xFFFFFFFF, rs0, 1);
            rs0 += __shfl_xor_sync(0xFFFFFFFF, rs0, 2);
            rs1 += __shfl_xor_sync(0xFFFFFFFF, rs1, 1);
            rs1 += __shfl_xor_sync(0xFFFFFFFF, rs1, 2);
            l0 = l0 * fac0 + rs0;  m0 = mn0;
            l1 = l1 * fac1 + rs1;  m1 = mn1;
            #pragma unroll
            for (int j = 0; j < 8; j++) {
                O[j][0] *= fac0; O[j][1] *= fac0;
                O[j][2] *= fac1; O[j][3] *= fac1;
            }

            uint32_t Pa[4][4];
            #pragma unroll
            for (int ks = 0; ks < 4; ks++) {
                const int j0 = 2 * ks, j1 = 2 * ks + 1;
                Pa[ks][0] = packh2(S[j0][0], S[j0][1]);
                Pa[ks][1] = packh2(S[j0][2], S[j0][3]);
                Pa[ks][2] = packh2(S[j1][0], S[j1][1]);
                Pa[ks][3] = packh2(S[j1][2], S[j1][3]);
            }
            #pragma unroll
            for (int ks = 0; ks < 4; ks++) {
                #pragma unroll
                for (int dp = 0; dp < 4; dp++) {
                    uint32_t Vb[4];
                    LDSM_X4_T(Vb[0], Vb[1], Vb[2], Vb[3],
                              stV + voff + (uint32_t)(ks * 16 * PL) + dp * 32);
                    mma_f16(O[2 * dp],     Pa[ks][0], Pa[ks][1], Pa[ks][2], Pa[ks][3],
                            Vb[0], Vb[1]);
                    mma_f16(O[2 * dp + 1], Pa[ks][0], Pa[ks][1], Pa[ks][2], Pa[ks][3],
                            Vb[2], Vb[3]);
                }
            }
        }
    }

    const float inv0 = 1.0f / l0, inv1 = 1.0f / l1;
    const int b_ = bh >> 4, h_ = bh & 15;
    __half* o0 = g_ha + (size_t)(b_ * TT + trow0) * DD + h_ * 64;
    __half* o1 = g_ha + (size_t)(b_ * TT + trow1) * DD + h_ * 64;
    #pragma unroll
    for (int j = 0; j < 8; j++) {
        const int col = j * 8 + tig * 2;
        *(__half2*)(o0 + col) = __floats2half2_rn(O[j][0] * inv0, O[j][1] * inv0);
        *(__half2*)(o1 + col) = __floats2half2_rn(O[j][2] * inv1, O[j][3] * inv1);
    }
}

// ---------------- loss: reduce per-block partials ----------------
// Padding lanes use -FLT_MAX (finite) so -INF minus -INF NaN cannot occur.
__global__ __launch_bounds__(256)
void k_loss_rows(const float* __restrict__ logits, const int* __restrict__ targets)
{
    const int r = blockIdx.x;
    const int tid = threadIdx.x;
    __shared__ float sm[256], ss[256];

    float m = -FLT_MAX, s = 0.0f;
    if (tid < NBLK) {
        const float2 p = g_pml[(size_t)r * NBLK + tid];
        m = p.x; s = p.y;
    }
    sm[tid] = m; ss[tid] = s;
    __syncthreads();
    for (int k = 128; k > 0; k >>= 1) {
        if (tid < k) {
            float m1 = sm[tid], s1 = ss[tid];
            float m2 = sm[tid + k], s2 = ss[tid + k];
            float M = fmaxf(m1, m2);
            ss[tid] = s1 * __expf(m1 - M) + s2 * __expf(m2 - M);
            sm[tid] = M;
        }
        __syncthreads();
    }
    if (tid == 0) {
        int tgt = targets[r];
        float logp = logits[(size_t)r * VV + tgt] - sm[0] - __logf(ss[0]);
        g_rowloss[r] = -logp;
    }
}

__global__ void k_loss_final(float* out)
{
    const int tid = threadIdx.x;
    __shared__ float red[256];
    float s = 0.0f;
    for (int i = tid; i < BT; i += 256) s += g_rowloss[i];
    red[tid] = s; __syncthreads();
    for (int k = 128; k > 0; k >>= 1) {
        if (tid < k) red[tid] += red[tid + k];
        __syncthreads();
    }
    if (tid == 0) out[0] = red[0] * (1.0f / BT);
}

// ---------------- launch ----------------
extern "C" void kernel_launch(void* const* d_in, const int* in_sizes, int n_in,
                              void* d_out, int out_size)
{
    const int*   ids     = (const int*)  d_in[0];
    const int*   targets = (const int*)  d_in[1];
    const float* tok_emb = (const float*)d_in[2];
    const float* pos_emb = (const float*)d_in[3];
    const float* Wq      = (const float*)d_in[4];
    const float* bq      = (const float*)d_in[5];
    const float* Wk      = (const float*)d_in[6];
    const float* bk      = (const float*)d_in[7];
    const float* Wv      = (const float*)d_in[8];
    const float* bv      = (const float*)d_in[9];
    const float* Wo      = (const float*)d_in[10];
    const float* bo      = (const float*)d_in[11];
    float* out = (float*)d_out;

    __half *px16, *pw16, *pha, *phb;
    cudaGetSymbolAddress((void**)&px16, g_x16);
    cudaGetSymbolAddress((void**)&pw16, g_w16);
    cudaGetSymbolAddress((void**)&pha,  g_ha);
    cudaGetSymbolAddress((void**)&phb,  g_hb);

    cudaFuncSetAttribute(k_gemm_qkv16,  cudaFuncAttributeMaxDynamicSharedMemorySize, FSMEM);
    cudaFuncSetAttribute(k_gemm_logits, cudaFuncAttributeMaxDynamicSharedMemorySize, F2SMEM);
    cudaFuncSetAttribute(k_flash_tc,    cudaFuncAttributeMaxDynamicSharedMemorySize, FL2_SMEM);

    // 1. embed + weight repacks (all fp16)
    k_embed16<<<BT, 256>>>(ids, tok_emb, pos_emb);
    k_repack_wqkvT<<<dim3(48, 32, 2), dim3(32, 8)>>>(Wq, Wk, Wv);
    k_woT<<<dim3(VV / 32, DD / 32), dim3(32, 8)>>>(Wo);

    // 2. QKV projection (fp16) -> fp16 head-major q/k/v (direct bias)
    k_gemm_qkv16<<<dim3(BT / 128, N3 / 128), 256, FSMEM>>>(px16, pw16, bq, bk, bv);

    // 3. tensor-core flash attention (emits fp16 A for the logits GEMM)
    k_flash_tc<<<dim3(8, BHN), 256, FL2_SMEM>>>();

    // 4. logits (fp16, 128x256 tiles) + fused loss partials
    k_gemm_logits<<<dim3(BT / 128, VV / 256), 256, F2SMEM>>>(pha, phb, out, bo);

    // 5. loss (partials reduce + mean)
    if ((long long)out_size > BTV) {
        k_loss_rows<<<BT, 256>>>(out, targets);
        k_loss_final<<<1, 256>>>(out + BTV);
    }
}